// round 3
// baseline (speedup 1.0000x reference)
#include <cuda_runtime.h>
#include <cstdint>

// Problem constants (LaplacianReg: B=32, V=65536, K=8, C=3)
#define BB 32
#define VV 65536
#define KK 8
#define CC 3
#define ROW (VV * CC)          // 196608 floats per batch row
#define VB (BB * CC)           // 96 floats per vertex in transposed scratch

// Scratch: d_t[v][b][c] = out[b][v][c] - tgt[b][v][c], 24 MB static device array.
__device__ float d_scratch[(size_t)VV * VB];

// ---------------------------------------------------------------------------
// Kernel 1: fused difference + transpose (B,V,C) -> (V,B,C)
// Tile: 32 vertices x 32 batches. Both global read and write fully coalesced.
// ---------------------------------------------------------------------------
__global__ __launch_bounds__(256) void diff_transpose_kernel(
    const float* __restrict__ outp, const float* __restrict__ tgtp) {
    __shared__ float s[32 * 97];   // stride 97 to break bank conflicts

    const int v0   = blockIdx.x * 32;
    const int warp = threadIdx.x >> 5;
    const int lane = threadIdx.x & 31;

    // Phase A: each warp loads 4 batch-rows (96 contiguous floats each), coalesced.
    #pragma unroll
    for (int i = 0; i < 4; i++) {
        const int b = warp + 8 * i;               // 0..31
        const float* po = outp + (size_t)b * ROW + (size_t)v0 * CC;
        const float* pt = tgtp + (size_t)b * ROW + (size_t)v0 * CC;
        #pragma unroll
        for (int r = 0; r < 3; r++) {
            const int u = lane + 32 * r;          // 0..95
            s[b * 97 + u] = po[u] - pt[u];
        }
    }
    __syncthreads();

    // Phase B: each warp stores 4 vertex-rows (96 contiguous floats each), coalesced.
    #pragma unroll
    for (int i = 0; i < 4; i++) {
        const int vl = warp + 8 * i;              // 0..31
        float* pd = d_scratch + (size_t)(v0 + vl) * VB;
        #pragma unroll
        for (int r = 0; r < 3; r++) {
            const int u = lane + 32 * r;          // 0..95 -> (b = u/3, c = u%3)
            const int b = u / 3;
            const int c = u - 3 * b;
            pd[u] = s[b * 97 + vl * 3 + c];       // <=3-way bank conflict
        }
    }
}

// ---------------------------------------------------------------------------
// Kernel 2: laplacian + square.
// Warp layout: lane = batch b (B==32), each warp owns 4 consecutive vertices.
// Gathers hit d_t[v][b][c]: one (v,k) gather by a warp = 12 fully-used 32B
// sectors. All K gathers issued before the FMA chain (high MLP to hide
// L2/DRAM latency). Output: each lane writes 12 contiguous floats = 3x STG.128.
// ---------------------------------------------------------------------------
__global__ __launch_bounds__(256) void lap_sq_kernel(
    const int*   __restrict__ idx,
    const float* __restrict__ wgt,
    float*       __restrict__ res) {
    const int warp = threadIdx.x >> 5;
    const int lane = threadIdx.x & 31;            // lane == batch index b
    const int v0   = blockIdx.x * 32 + warp * 4;

    float r[12];

    #pragma unroll
    for (int vi = 0; vi < 4; vi++) {
        const int v = v0 + vi;

        // Uniform (warp-broadcast) vector loads of the 8 neighbor ids + weights.
        const int4   j01 = *reinterpret_cast<const int4*>(idx + (size_t)v * KK);
        const int4   j23 = *reinterpret_cast<const int4*>(idx + (size_t)v * KK + 4);
        const float4 w01 = *reinterpret_cast<const float4*>(wgt + (size_t)v * KK);
        const float4 w23 = *reinterpret_cast<const float4*>(wgt + (size_t)v * KK + 4);
        const int   js[8] = {j01.x, j01.y, j01.z, j01.w, j23.x, j23.y, j23.z, j23.w};
        const float ws[8] = {w01.x, w01.y, w01.z, w01.w, w23.x, w23.y, w23.z, w23.w};

        // Issue ALL gather loads up front (self + 8 neighbors): MLP ~= 27.
        const float* dv = d_scratch + (size_t)v * VB + lane * CC;
        float a0 = dv[0];
        float a1 = dv[1];
        float a2 = dv[2];

        float g0[8], g1[8], g2[8];
        #pragma unroll
        for (int k = 0; k < KK; k++) {
            const float* dj = d_scratch + (size_t)js[k] * VB + lane * CC;
            g0[k] = dj[0];
            g1[k] = dj[1];
            g2[k] = dj[2];
        }

        #pragma unroll
        for (int k = 0; k < KK; k++) {
            const float wk = ws[k];
            a0 = fmaf(wk, g0[k], a0);
            a1 = fmaf(wk, g1[k], a1);
            a2 = fmaf(wk, g2[k], a2);
        }
        r[vi * 3 + 0] = a0 * a0;
        r[vi * 3 + 1] = a1 * a1;
        r[vi * 3 + 2] = a2 * a2;
    }

    // lane b writes out[b, v0:v0+4, 0:3] = 12 contiguous floats, 16B-aligned.
    float4* o = reinterpret_cast<float4*>(res + (size_t)lane * ROW + (size_t)v0 * CC);
    o[0] = make_float4(r[0], r[1], r[2],  r[3]);
    o[1] = make_float4(r[4], r[5], r[6],  r[7]);
    o[2] = make_float4(r[8], r[9], r[10], r[11]);
}

extern "C" void kernel_launch(void* const* d_in, const int* in_sizes, int n_in,
                              void* d_out, int out_size) {
    const float* outp = (const float*)d_in[0];
    const float* tgtp = (const float*)d_in[1];
    const int*   idx  = (const int*)  d_in[2];
    const float* wgt  = (const float*)d_in[3];
    float*       res  = (float*)d_out;

    (void)in_sizes; (void)n_in; (void)out_size;

    diff_transpose_kernel<<<VV / 32, 256>>>(outp, tgtp);
    lap_sq_kernel<<<VV / 32, 256>>>(idx, wgt, res);
}